// round 10
// baseline (speedup 1.0000x reference)
#include <cuda_runtime.h>
#include <cuda_fp16.h>
#include <cstdint>

#define N_BLOCKS   512
#define BLOCK_IN   128
#define BLOCK_OUT  128
#define LAYER_IN   65536
#define LAYER_OUT  65536
#define BATCH      2048

// softmax(c) as fp16, row-major [n][m][o]  (m = K dim, o = N dim)
__device__ __align__(16) __half g_w[(size_t)N_BLOCKS * BLOCK_IN * BLOCK_OUT];

__device__ __forceinline__ uint32_t smem_u32(const void* p) {
    uint32_t a;
    asm("{ .reg .u64 t; cvta.to.shared.u64 t, %1; cvt.u32.u64 %0, t; }" : "=r"(a) : "l"(p));
    return a;
}

// ---------------------------------------------------------------------------
// Pass 1: softmax over m for each (n, o); write fp16 w[m][o].
// ---------------------------------------------------------------------------
__global__ __launch_bounds__(512) void softmax_kernel(const float* __restrict__ c) {
    extern __shared__ float sm[];
    float* se   = sm;            // [128][128] exp cache (64KB)
    float* psum = sm + 16384;    // [16][128] partial sums (8KB)

    const int n  = blockIdx.x;
    const int tid = threadIdx.x;
    const int o4 = (tid & 31) * 4;
    const int q  = tid >> 5;                 // 0..15, owns m = q*8 .. q*8+7
    const float* cn = c + (size_t)n * (BLOCK_IN * BLOCK_OUT);

    float4 s = make_float4(0.f, 0.f, 0.f, 0.f);
#pragma unroll
    for (int j = 0; j < 8; j++) {
        int m = q * 8 + j;
        float4 v = *(const float4*)(cn + m * 128 + o4);
        float4 e = make_float4(__expf(v.x), __expf(v.y), __expf(v.z), __expf(v.w));
        *(float4*)(se + m * 128 + o4) = e;
        s.x += e.x; s.y += e.y; s.z += e.z; s.w += e.w;
    }
    *(float4*)(psum + q * 128 + o4) = s;
    __syncthreads();

    float4 tot = make_float4(0.f, 0.f, 0.f, 0.f);
#pragma unroll
    for (int k = 0; k < 16; k++) {
        float4 p = *(const float4*)(psum + k * 128 + o4);
        tot.x += p.x; tot.y += p.y; tot.z += p.z; tot.w += p.w;
    }
    float4 inv = make_float4(1.f / tot.x, 1.f / tot.y, 1.f / tot.z, 1.f / tot.w);

    __half* w = g_w + (size_t)n * (BLOCK_IN * BLOCK_OUT);
#pragma unroll
    for (int j = 0; j < 8; j++) {
        int m = q * 8 + j;
        float4 e = *(const float4*)(se + m * 128 + o4);
        __half2 h01 = __floats2half2_rn(e.x * inv.x, e.y * inv.y);
        __half2 h23 = __floats2half2_rn(e.z * inv.z, e.w * inv.w);
        uint2 pk = make_uint2(*(uint32_t*)&h01, *(uint32_t*)&h23);
        *(uint2*)(w + m * 128 + o4) = pk;
    }
}

// ---------------------------------------------------------------------------
// Pass 2: per (n, 4 batch-tiles) GEMM via mma.sync m16n8k16 fp16.
// 4 warps, warp tile 64x64. sA double-buffered; whole next tile prefetched
// as one batched burst at the TOP of the compute phase. One barrier per tile.
// ---------------------------------------------------------------------------
#define LDA 136                      // halfs per padded smem row (128 + 8)
#define A_TILE_HALFS (128 * LDA)     // 34816 B
#define SMEM_TOTAL (3 * A_TILE_HALFS * 2)   // sB + sA0 + sA1 = 104448 B
#define BT_PER_CTA 4

#define LDSM_X4(R0, R1, R2, R3, ADDR)                                          \
    asm volatile("ldmatrix.sync.aligned.m8n8.x4.shared.b16 {%0,%1,%2,%3}, [%4];" \
                 : "=r"(R0), "=r"(R1), "=r"(R2), "=r"(R3) : "r"(ADDR))

#define LDSM_X4_T(R0, R1, R2, R3, ADDR)                                        \
    asm volatile("ldmatrix.sync.aligned.m8n8.x4.trans.shared.b16 {%0,%1,%2,%3}, [%4];" \
                 : "=r"(R0), "=r"(R1), "=r"(R2), "=r"(R3) : "r"(ADDR))

#define MMA16816(D, A, B0, B1)                                                 \
    asm volatile("mma.sync.aligned.m16n8k16.row.col.f32.f16.f16.f32 "          \
                 "{%0,%1,%2,%3}, {%4,%5,%6,%7}, {%8,%9}, {%0,%1,%2,%3};"       \
                 : "+f"((D)[0]), "+f"((D)[1]), "+f"((D)[2]), "+f"((D)[3])      \
                 : "r"((A)[0]), "r"((A)[1]), "r"((A)[2]), "r"((A)[3]),         \
                   "r"(B0), "r"(B1))

// 128 threads, streaming loads (x has zero reuse)
__device__ __forceinline__ void load_a_tile(const float* __restrict__ xb, __half* sA, int tid) {
#pragma unroll
    for (int i = 0; i < 32; i++) {
        int idx = tid + i * 128;              // 0..4095
        int r   = idx >> 5;
        int k4  = (idx & 31) << 2;
        float4 v = __ldcs((const float4*)(xb + (size_t)r * LAYER_IN + k4));
        __half2 h01 = __floats2half2_rn(v.x, v.y);
        __half2 h23 = __floats2half2_rn(v.z, v.w);
        uint2 pk = make_uint2(*(uint32_t*)&h01, *(uint32_t*)&h23);
        *(uint2*)&sA[r * LDA + k4] = pk;
    }
}

__global__ __launch_bounds__(128, 2)
void gemm_kernel(const float* __restrict__ x, float* __restrict__ out) {
    extern __shared__ __half smem[];
    __half* sB = smem;
    __half* sAbuf[2] = { smem + A_TILE_HALFS, smem + 2 * A_TILE_HALFS };

    const int tid  = threadIdx.x;
    const int wid  = tid >> 5;
    const int lane = tid & 31;
    const int n    = blockIdx.x;
    const int btg  = blockIdx.y;

    // ---- load w tile [128 k x 128 o] fp16 -> padded smem (once per CTA) ----
    {
        const uint4* wsrc = (const uint4*)(g_w + (size_t)n * (BLOCK_IN * BLOCK_OUT));
#pragma unroll
        for (int i = 0; i < 16; i++) {
            int idx = tid + i * 128;          // 0..2047
            int r   = idx >> 4;
            int c   = (idx & 15) << 3;
            *(uint4*)&sB[r * LDA + c] = wsrc[idx];
        }
    }
    // ---- first A tile ----
    const float* xcol = x + (size_t)n * 128;
    load_a_tile(xcol + (size_t)(btg * BT_PER_CTA * 128) * LAYER_IN, sAbuf[0], tid);
    __syncthreads();

    const int warp_m = wid & 1;
    const int warp_n = wid >> 1;
    const int lr = lane & 15;
    const int lc = (lane >> 4) << 3;

    for (int t = 0; t < BT_PER_CTA; t++) {
        const int bt = btg * BT_PER_CTA + t;
        __half* sA  = sAbuf[t & 1];
        __half* sAn = sAbuf[(t + 1) & 1];

        // ---- prefetch next tile at TOP of compute: burst drains under MMAs ----
        if (t + 1 < BT_PER_CTA) {
            load_a_tile(xcol + (size_t)((bt + 1) * 128) * LAYER_IN, sAn, tid);
        }

        float acc[4][8][4];
#pragma unroll
        for (int mt = 0; mt < 4; mt++)
#pragma unroll
            for (int nt = 0; nt < 8; nt++)
#pragma unroll
                for (int j = 0; j < 4; j++) acc[mt][nt][j] = 0.f;

#pragma unroll
        for (int ks = 0; ks < 8; ks++) {
            const int k = ks * 16;

            uint32_t a[4][4];
#pragma unroll
            for (int mt = 0; mt < 4; mt++) {
                int row = warp_m * 64 + mt * 16 + lr;
                uint32_t addr = smem_u32(&sA[row * LDA + k + lc]);
                LDSM_X4(a[mt][0], a[mt][1], a[mt][2], a[mt][3], addr);
            }

            uint32_t b[8][2];
#pragma unroll
            for (int qq = 0; qq < 4; qq++) {
                int nn = warp_n * 64 + qq * 16;
                uint32_t addr = smem_u32(&sB[(k + lr) * LDA + nn + lc]);
                LDSM_X4_T(b[qq * 2][0], b[qq * 2][1], b[qq * 2 + 1][0], b[qq * 2 + 1][1], addr);
            }

#pragma unroll
            for (int mt = 0; mt < 4; mt++)
#pragma unroll
                for (int nt = 0; nt < 8; nt++)
                    MMA16816(acc[mt][nt], a[mt], b[nt][0], b[nt][1]);
        }

        // ---- epilogue: streaming float2 stores (out never re-read) ----
        float* obase = out + (size_t)(bt * 128) * LAYER_OUT + (size_t)n * 128;
        const int er = lane >> 2;
        const int ec = (lane & 3) << 1;
#pragma unroll
        for (int mt = 0; mt < 4; mt++) {
#pragma unroll
            for (int nt = 0; nt < 8; nt++) {
                int r0 = warp_m * 64 + mt * 16 + er;
                int c0 = warp_n * 64 + nt * 8 + ec;
                __stcs((float2*)(obase + (size_t)r0 * LAYER_OUT + c0),
                       make_float2(acc[mt][nt][0], acc[mt][nt][1]));
                __stcs((float2*)(obase + (size_t)(r0 + 8) * LAYER_OUT + c0),
                       make_float2(acc[mt][nt][2], acc[mt][nt][3]));
            }
        }

        // one barrier per tile: prefetch STS visible + all reads of sA done
        __syncthreads();
    }
}

// ---------------------------------------------------------------------------
extern "C" void kernel_launch(void* const* d_in, const int* in_sizes, int n_in,
                              void* d_out, int out_size) {
    (void)in_sizes; (void)n_in; (void)out_size;
    const float* x = (const float*)d_in[0];
    const float* c = (const float*)d_in[1];
    float* out = (float*)d_out;

    cudaFuncSetAttribute(softmax_kernel, cudaFuncAttributeMaxDynamicSharedMemorySize, 73728);
    cudaFuncSetAttribute(gemm_kernel,    cudaFuncAttributeMaxDynamicSharedMemorySize, SMEM_TOTAL);

    softmax_kernel<<<N_BLOCKS, 512, 73728>>>(c);
    gemm_kernel<<<dim3(N_BLOCKS, BATCH / 128 / BT_PER_CTA), 128, SMEM_TOTAL>>>(x, out);
}

// round 11
// speedup vs baseline: 2.0593x; 2.0593x over previous
#include <cuda_runtime.h>
#include <cuda_fp16.h>
#include <cstdint>

#define N_BLOCKS   512
#define BLOCK_IN   128
#define BLOCK_OUT  128
#define LAYER_IN   65536
#define LAYER_OUT  65536
#define BATCH      2048

// softmax(c) as fp16, row-major [n][m][o]  (m = K dim, o = N dim)
__device__ __align__(16) __half g_w[(size_t)N_BLOCKS * BLOCK_IN * BLOCK_OUT];

__device__ __forceinline__ uint32_t smem_u32(const void* p) {
    uint32_t a;
    asm("{ .reg .u64 t; cvta.to.shared.u64 t, %1; cvt.u32.u64 %0, t; }" : "=r"(a) : "l"(p));
    return a;
}

// ---------------------------------------------------------------------------
// Pass 1: softmax over m for each (n, o); write fp16 w[m][o].  (unchanged)
// ---------------------------------------------------------------------------
__global__ __launch_bounds__(512) void softmax_kernel(const float* __restrict__ c) {
    extern __shared__ float sm[];
    float* se   = sm;
    float* psum = sm + 16384;

    const int n  = blockIdx.x;
    const int tid = threadIdx.x;
    const int o4 = (tid & 31) * 4;
    const int q  = tid >> 5;
    const float* cn = c + (size_t)n * (BLOCK_IN * BLOCK_OUT);

    float4 s = make_float4(0.f, 0.f, 0.f, 0.f);
#pragma unroll
    for (int j = 0; j < 8; j++) {
        int m = q * 8 + j;
        float4 v = *(const float4*)(cn + m * 128 + o4);
        float4 e = make_float4(__expf(v.x), __expf(v.y), __expf(v.z), __expf(v.w));
        *(float4*)(se + m * 128 + o4) = e;
        s.x += e.x; s.y += e.y; s.z += e.z; s.w += e.w;
    }
    *(float4*)(psum + q * 128 + o4) = s;
    __syncthreads();

    float4 tot = make_float4(0.f, 0.f, 0.f, 0.f);
#pragma unroll
    for (int k = 0; k < 16; k++) {
        float4 p = *(const float4*)(psum + k * 128 + o4);
        tot.x += p.x; tot.y += p.y; tot.z += p.z; tot.w += p.w;
    }
    float4 inv = make_float4(1.f / tot.x, 1.f / tot.y, 1.f / tot.z, 1.f / tot.w);

    __half* w = g_w + (size_t)n * (BLOCK_IN * BLOCK_OUT);
#pragma unroll
    for (int j = 0; j < 8; j++) {
        int m = q * 8 + j;
        float4 e = *(const float4*)(se + m * 128 + o4);
        __half2 h01 = __floats2half2_rn(e.x * inv.x, e.y * inv.y);
        __half2 h23 = __floats2half2_rn(e.z * inv.z, e.w * inv.w);
        uint2 pk = make_uint2(*(uint32_t*)&h01, *(uint32_t*)&h23);
        *(uint2*)(w + m * 128 + o4) = pk;
    }
}

// ---------------------------------------------------------------------------
// Pass 2: cp.async-pipelined GEMM. 256 threads, 8 warps, warp tile 64x32.
// x tile staged as raw fp32 via cp.async (drains under MMAs), then a short
// smem->smem convert produces the fp16 sA. 1 CTA/SM (132KB smem).
// ---------------------------------------------------------------------------
#define LDA 136                        // halfs per padded smem row
#define STAGE_BYTES 65536              // 128x128 fp32, linear
#define SA_BYTES    (128 * LDA * 2)    // 34816
#define SB_BYTES    (128 * LDA * 2)    // 34816
#define SMEM_TOTAL  (STAGE_BYTES + SA_BYTES + SB_BYTES)   // 135168
#define BT_PER_CTA 8

#define LDSM_X4(R0, R1, R2, R3, ADDR)                                          \
    asm volatile("ldmatrix.sync.aligned.m8n8.x4.shared.b16 {%0,%1,%2,%3}, [%4];" \
                 : "=r"(R0), "=r"(R1), "=r"(R2), "=r"(R3) : "r"(ADDR))

#define LDSM_X4_T(R0, R1, R2, R3, ADDR)                                        \
    asm volatile("ldmatrix.sync.aligned.m8n8.x4.trans.shared.b16 {%0,%1,%2,%3}, [%4];" \
                 : "=r"(R0), "=r"(R1), "=r"(R2), "=r"(R3) : "r"(ADDR))

#define MMA16816(D, A, B0, B1)                                                 \
    asm volatile("mma.sync.aligned.m16n8k16.row.col.f32.f16.f16.f32 "          \
                 "{%0,%1,%2,%3}, {%4,%5,%6,%7}, {%8,%9}, {%0,%1,%2,%3};"       \
                 : "+f"((D)[0]), "+f"((D)[1]), "+f"((D)[2]), "+f"((D)[3])      \
                 : "r"((A)[0]), "r"((A)[1]), "r"((A)[2]), "r"((A)[3]),         \
                   "r"(B0), "r"(B1))

__device__ __forceinline__ void cp16(uint32_t dst_smem, const void* src) {
    asm volatile("cp.async.cg.shared.global [%0], [%1], 16;" :: "r"(dst_smem), "l"(src));
}
#define CP_COMMIT() asm volatile("cp.async.commit_group;" ::: "memory")
#define CP_WAIT0()  asm volatile("cp.async.wait_group 0;" ::: "memory")

// issue 16 cp.asyncs per thread: x tile [128 x 128] fp32 -> linear stage
__device__ __forceinline__ void stage_x(const float* __restrict__ xb, uint32_t stage_s, int tid) {
#pragma unroll
    for (int i = 0; i < 16; i++) {
        int idx = tid + i * 256;               // 0..4095 (16B chunks)
        int r   = idx >> 5;
        int k4  = (idx & 31) << 2;
        cp16(stage_s + idx * 16, xb + (size_t)r * LAYER_IN + k4);
    }
}

// smem->smem: fp32 stage -> fp16 padded sA
__device__ __forceinline__ void convert_stage(const float* stage, __half* sA, int tid) {
#pragma unroll
    for (int i = 0; i < 16; i++) {
        int idx = tid + i * 256;
        float4 v = *(const float4*)(stage + idx * 4);
        int r  = idx >> 5;
        int k4 = (idx & 31) << 2;
        __half2 h01 = __floats2half2_rn(v.x, v.y);
        __half2 h23 = __floats2half2_rn(v.z, v.w);
        uint2 pk = make_uint2(*(uint32_t*)&h01, *(uint32_t*)&h23);
        *(uint2*)&sA[r * LDA + k4] = pk;
    }
}

__global__ __launch_bounds__(256, 1)
void gemm_kernel(const float* __restrict__ x, float* __restrict__ out) {
    extern __shared__ char smem[];
    float* stage = (float*)smem;
    __half* sA = (__half*)(smem + STAGE_BYTES);
    __half* sB = (__half*)(smem + STAGE_BYTES + SA_BYTES);
    const uint32_t stage_s = smem_u32(stage);

    const int tid  = threadIdx.x;
    const int wid  = tid >> 5;
    const int lane = tid & 31;
    const int n    = blockIdx.x;
    const int btg  = blockIdx.y;

    const float* xcol = x + (size_t)n * 128;
    const __half* wsrc = g_w + (size_t)n * (BLOCK_IN * BLOCK_OUT);

    // ---- prologue: cp.async w -> sB and x(tile0) -> stage ----
    {
        uint32_t sB_s = smem_u32(sB);
#pragma unroll
        for (int i = 0; i < 8; i++) {
            int idx = tid + i * 256;           // 0..2047
            int r   = idx >> 4;
            int c   = (idx & 15) << 3;
            cp16(sB_s + (r * LDA + c) * 2, wsrc + idx * 8);
        }
    }
    stage_x(xcol + (size_t)(btg * BT_PER_CTA * 128) * LAYER_IN, stage_s, tid);
    CP_COMMIT();
    CP_WAIT0();
    __syncthreads();
    convert_stage(stage, sA, tid);
    __syncthreads();

    // 8 warps: 2 (m) x 4 (n); warp tile 64x32
    const int warp_m = wid & 1;
    const int warp_n = wid >> 1;
    const int lr = lane & 15;
    const int lc = (lane >> 4) << 3;

    for (int t = 0; t < BT_PER_CTA; t++) {
        const int bt = btg * BT_PER_CTA + t;
        const bool pf = (t + 1 < BT_PER_CTA);

        // ---- prefetch next x tile: cp.async drains under the k-loop ----
        if (pf) {
            stage_x(xcol + (size_t)((bt + 1) * 128) * LAYER_IN, stage_s, tid);
            CP_COMMIT();
        }

        float acc[4][4][4];
#pragma unroll
        for (int mt = 0; mt < 4; mt++)
#pragma unroll
            for (int nt = 0; nt < 4; nt++)
#pragma unroll
                for (int j = 0; j < 4; j++) acc[mt][nt][j] = 0.f;

#pragma unroll
        for (int ks = 0; ks < 8; ks++) {
            const int k = ks * 16;

            uint32_t a[4][4];
#pragma unroll
            for (int mt = 0; mt < 4; mt++) {
                int row = warp_m * 64 + mt * 16 + lr;
                uint32_t addr = smem_u32(&sA[row * LDA + k + lc]);
                LDSM_X4(a[mt][0], a[mt][1], a[mt][2], a[mt][3], addr);
            }

            uint32_t b[4][2];
#pragma unroll
            for (int qq = 0; qq < 2; qq++) {
                int nn = warp_n * 32 + qq * 16;
                uint32_t addr = smem_u32(&sB[(k + lr) * LDA + nn + lc]);
                LDSM_X4_T(b[qq * 2][0], b[qq * 2][1], b[qq * 2 + 1][0], b[qq * 2 + 1][1], addr);
            }

#pragma unroll
            for (int mt = 0; mt < 4; mt++)
#pragma unroll
                for (int nt = 0; nt < 4; nt++)
                    MMA16816(acc[mt][nt], a[mt], b[nt][0], b[nt][1]);
        }

        // ---- all async copies landed + all warps done reading sA ----
        CP_WAIT0();
        __syncthreads();

        // ---- convert staged fp32 -> fp16 sA for next tile (short, smem-local) ----
        if (pf) convert_stage(stage, sA, tid);

        // ---- epilogue: coalesced float2 stores (overlaps convert drain) ----
        float* obase = out + (size_t)(bt * 128) * LAYER_OUT + (size_t)n * 128;
        const int er = lane >> 2;
        const int ec = (lane & 3) << 1;
#pragma unroll
        for (int mt = 0; mt < 4; mt++) {
#pragma unroll
            for (int nt = 0; nt < 4; nt++) {
                int r0 = warp_m * 64 + mt * 16 + er;
                int c0 = warp_n * 32 + nt * 8 + ec;
                *(float2*)(obase + (size_t)r0 * LAYER_OUT + c0) =
                    make_float2(acc[mt][nt][0], acc[mt][nt][1]);
                *(float2*)(obase + (size_t)(r0 + 8) * LAYER_OUT + c0) =
                    make_float2(acc[mt][nt][2], acc[mt][nt][3]);
            }
        }

        __syncthreads();   // sA writes visible before next k-loop
    }
}

// ---------------------------------------------------------------------------
extern "C" void kernel_launch(void* const* d_in, const int* in_sizes, int n_in,
                              void* d_out, int out_size) {
    (void)in_sizes; (void)n_in; (void)out_size;
    const float* x = (const float*)d_in[0];
    const float* c = (const float*)d_in[1];
    float* out = (float*)d_out;

    cudaFuncSetAttribute(softmax_kernel, cudaFuncAttributeMaxDynamicSharedMemorySize, 73728);
    cudaFuncSetAttribute(gemm_kernel,    cudaFuncAttributeMaxDynamicSharedMemorySize, SMEM_TOTAL);

    softmax_kernel<<<N_BLOCKS, 512, 73728>>>(c);
    gemm_kernel<<<dim3(N_BLOCKS, BATCH / 128 / BT_PER_CTA), 256, SMEM_TOTAL>>>(x, out);
}